// round 1
// baseline (speedup 1.0000x reference)
#include <cuda_runtime.h>
#include <math.h>

// Problem constants (Disentangler_18425409700171)
#define T_     8
#define NTOK_  32768
#define D_     128
#define L_     8
#define CD_    64
#define TILE_  128
#define XSTR   132   // padded smem row stride (floats)

// -------- device scratch (no allocations allowed) --------
__device__ float g_hsum[T_ * L_ * D_];   // per-(t,l) sum of gelu-hidden over real tokens
__device__ int   g_cnt [T_ * L_];        // real-token counts per (t,l)
__device__ float g_comp[T_ * L_ * CD_];  // comp[t][l][c]

__device__ __forceinline__ float gelu_exact(float z) {
    return 0.5f * z * (1.0f + erff(z * 0.70710678118654752440f));
}

__device__ __forceinline__ float wred(float v) {
    #pragma unroll
    for (int o = 16; o; o >>= 1) v += __shfl_down_sync(0xffffffffu, v, o);
    return v;
}

// -------- kernel 0: zero accumulators (required per graph replay) --------
__global__ void k_zero() {
    int tid = threadIdx.x;
    for (int i = tid; i < T_ * L_ * D_; i += blockDim.x) g_hsum[i] = 0.f;
    if (tid < T_ * L_) g_cnt[tid] = 0;
}

// -------- kernel 1: LN -> x@w1+b1 -> gelu -> per-group column sums --------
__global__ __launch_bounds__(512) void k_main(
    const float* __restrict__ x,   const float* __restrict__ lnw,
    const float* __restrict__ lnb, const float* __restrict__ w1,
    const float* __restrict__ b1,  const int*   __restrict__ node_idx,
    const int*   __restrict__ ne_p)
{
    extern __shared__ float sm[];
    float* xs     = sm;                        // 128 x 132  (x tile, then reused for H)
    float* w1s    = xs + TILE_ * XSTR;         // 128 x 132
    float* bucket = w1s + D_ * XSTR;           // 8 x 128
    int*   gid    = (int*)(bucket + L_ * D_);  // 128

    const int tid  = threadIdx.x;
    const int t    = blockIdx.y;
    const int base = blockIdx.x * TILE_;
    const int g    = ne_p[0] / L_;             // slots per group

    // ---- loads: x tile + w1, float4 vectorized ----
    const float4* x4  = (const float4*)(x + ((size_t)t * NTOK_ + base) * D_);
    const float4* w14 = (const float4*)w1;
    #pragma unroll
    for (int it = 0; it < 8; ++it) {
        int v = tid + it * 512;
        int r = v >> 5, c4 = v & 31;
        float4 a = x4[r * 32 + c4];
        *(float4*)(xs  + r * XSTR + c4 * 4) = a;
        float4 b = w14[v];
        *(float4*)(w1s + r * XSTR + c4 * 4) = b;
    }
    if (tid < TILE_) gid[tid] = node_idx[t * NTOK_ + base + tid] / g;
    for (int i = tid; i < L_ * D_; i += 512) bucket[i] = 0.f;
    __syncthreads();

    // ---- per-row LayerNorm (128 threads, one row each) ----
    if (tid < TILE_) {
        float* row = xs + tid * XSTR;
        float s = 0.f, s2 = 0.f;
        #pragma unroll 4
        for (int k = 0; k < D_; ++k) { float v = row[k]; s += v; s2 += v * v; }
        float m    = s  * (1.0f / D_);
        float var  = s2 * (1.0f / D_) - m * m;
        float rstd = rsqrtf(var + 1e-5f);
        #pragma unroll 4
        for (int k = 0; k < D_; ++k)
            row[k] = (row[k] - m) * rstd * lnw[k] + lnb[k];
    }
    __syncthreads();

    // ---- GEMM: H[128,128] = xn @ w1 (fp32, 8x4 microtile per thread) ----
    const int ty = tid >> 5;   // 0..15 (warp id)
    const int tx = tid & 31;   // lane
    float acc[8][4];
    #pragma unroll
    for (int i = 0; i < 8; ++i)
        #pragma unroll
        for (int j = 0; j < 4; ++j) acc[i][j] = 0.f;

    #pragma unroll 4
    for (int k = 0; k < D_; ++k) {
        float a[8], b[4];
        #pragma unroll
        for (int i = 0; i < 8; ++i) a[i] = xs[(ty + 16 * i) * XSTR + k];     // broadcast
        #pragma unroll
        for (int j = 0; j < 4; ++j) b[j] = w1s[k * XSTR + tx + 32 * j];      // conflict-free
        #pragma unroll
        for (int i = 0; i < 8; ++i)
            #pragma unroll
            for (int j = 0; j < 4; ++j) acc[i][j] = fmaf(a[i], b[j], acc[i][j]);
    }
    __syncthreads();   // all xs reads done before reuse as H

    // ---- bias + exact gelu, store H into xs region ----
    float bb[4];
    #pragma unroll
    for (int j = 0; j < 4; ++j) bb[j] = b1[tx + 32 * j];
    #pragma unroll
    for (int i = 0; i < 8; ++i)
        #pragma unroll
        for (int j = 0; j < 4; ++j)
            xs[(ty + 16 * i) * XSTR + tx + 32 * j] = gelu_exact(acc[i][j] + bb[j]);
    __syncthreads();

    // ---- per-group column sums: 512 threads, each 32 rows of one column ----
    {
        int c = tid & 127;
        int q = tid >> 7;
        float facc[8];
        #pragma unroll
        for (int l = 0; l < 8; ++l) facc[l] = 0.f;
        int r0 = q * 32;
        for (int r = r0; r < r0 + 32; ++r) {
            float h  = xs[r * XSTR + c];
            int   gr = gid[r];
            #pragma unroll
            for (int l = 0; l < 8; ++l) facc[l] += (gr == l) ? h : 0.f;  // no local-mem spill
        }
        #pragma unroll
        for (int l = 0; l < 8; ++l) atomicAdd(&bucket[l * D_ + c], facc[l]);
    }
    __syncthreads();

    // ---- flush to global ----
    for (int i = tid; i < L_ * D_; i += 512)
        atomicAdd(&g_hsum[(t * L_ + (i >> 7)) * D_ + (i & 127)], bucket[i]);
    if (tid < L_) {
        int n = 0;
        #pragma unroll 4
        for (int r = 0; r < TILE_; ++r) n += (gid[r] == tid);
        atomicAdd(&g_cnt[t * L_ + tid], n);
    }
}

// -------- kernel 2: comp[t][l][:] = ((hsum + zero_slots*h0)/g) @ w2 + b2 --------
__global__ void k_comp(const float* __restrict__ w2, const float* __restrict__ b1,
                       const float* __restrict__ b2, const int* __restrict__ ne_p)
{
    __shared__ float mh[D_];
    const int p   = blockIdx.x;           // t*8 + l
    const int tid = threadIdx.x;          // 128
    const int g   = ne_p[0] / L_;
    const float zslots = (float)(g - g_cnt[p]);
    if (tid < D_) {
        float h0 = gelu_exact(b1[tid]);
        mh[tid] = (g_hsum[p * D_ + tid] + zslots * h0) / (float)g;
    }
    __syncthreads();
    if (tid < CD_) {
        float acc = b2[tid];
        #pragma unroll 4
        for (int e = 0; e < D_; ++e) acc = fmaf(mh[e], w2[e * CD_ + tid], acc);
        g_comp[p * CD_ + tid] = acc;
    }
}

// -------- kernel 3: final LN + exact ortho loss --------
__global__ __launch_bounds__(512) void k_final(
    const float* __restrict__ lnfw, const float* __restrict__ lnfb,
    float* __restrict__ out, int out_size)
{
    __shared__ float cs[T_ * L_ * CD_];   // 4096: cs[t*512 + l*64 + c]
    __shared__ float inv[L_];
    __shared__ float dots[49];
    const int tid = threadIdx.x;
    for (int i = tid; i < T_ * L_ * CD_; i += 512) cs[i] = g_comp[i];
    __syncthreads();

    const int w = tid >> 5, lane = tid & 31;
    if (w < 8) {
        // final LayerNorm over 512 per t (contiguous in cs)
        const int t = w;
        const float* row = cs + t * 512;
        float s = 0.f;
        for (int i = lane; i < 512; i += 32) s += row[i];
        s = wred(s);
        float m = __shfl_sync(0xffffffffu, s, 0) * (1.0f / 512.0f);
        float v = 0.f;
        for (int i = lane; i < 512; i += 32) { float c0 = row[i] - m; v += c0 * c0; }
        v = wred(v);
        float rstd = rsqrtf(__shfl_sync(0xffffffffu, v, 0) * (1.0f / 512.0f) + 1e-5f);
        for (int i = lane; i < 512; i += 32)
            out[t * 512 + i] = (row[i] - m) * rstd * lnfw[i] + lnfb[i];
    } else {
        // f[l][k], k = t*64+c : inverse norms
        const int l = w - 8;
        float s = 0.f;
        for (int k = lane; k < 512; k += 32) {
            float v = cs[(k >> 6) * 512 + l * 64 + (k & 63)];
            s += v * v;
        }
        s = wred(s);
        if (lane == 0) inv[l] = rsqrtf(s);
    }
    __syncthreads();

    // exact reference pair loop: i in 0..6, j in 1..7 (includes i==j), 49 dots
    for (int p = w; p < 49; p += 16) {
        int i = p / 7, j = p % 7 + 1;
        float ii = inv[i], ij = inv[j];
        float num = 0.f, den = 0.f;
        for (int k = lane; k < 512; k += 32) {
            int off = (k >> 6) * 512 + (k & 63);
            float vi = cs[off + i * 64] * ii;
            float vj = cs[off + j * 64] * ij;
            num += vi * vj;
            den += vi + vj;
        }
        num = wred(num);
        den = wred(den);
        if (lane == 0) { float d = num / den; dots[p] = d * d; }
    }
    __syncthreads();
    if (tid == 0 && out_size > T_ * L_ * CD_) {
        float s = 0.f;
        #pragma unroll
        for (int p = 0; p < 49; ++p) s += dots[p];
        out[T_ * L_ * CD_] = s * (1.0f / 49.0f);
    }
}

// -------- launch --------
extern "C" void kernel_launch(void* const* d_in, const int* in_sizes, int n_in,
                              void* d_out, int out_size)
{
    const float* x    = (const float*)d_in[0];
    const float* lnw  = (const float*)d_in[1];
    const float* lnb  = (const float*)d_in[2];
    const float* w1   = (const float*)d_in[3];
    const float* b1   = (const float*)d_in[4];
    const float* w2   = (const float*)d_in[5];
    const float* b2   = (const float*)d_in[6];
    const float* lnfw = (const float*)d_in[7];
    const float* lnfb = (const float*)d_in[8];
    // d_in[9] = padded_node_mask (all-true by construction; masked token == zero row == zero slot)
    const int* node_idx = (const int*)d_in[10];
    const int* ne       = (const int*)d_in[11];
    float* out = (float*)d_out;

    size_t smem1 = (size_t)(TILE_ * XSTR + D_ * XSTR + L_ * D_) * sizeof(float)
                 + (size_t)TILE_ * sizeof(int);
    cudaFuncSetAttribute(k_main, cudaFuncAttributeMaxDynamicSharedMemorySize, (int)smem1);

    k_zero<<<1, 512>>>();
    dim3 grid(NTOK_ / TILE_, T_);
    k_main<<<grid, 512, smem1>>>(x, lnw, lnb, w1, b1, node_idx, ne);
    k_comp<<<T_ * L_, 128>>>(w2, b1, b2, ne);
    k_final<<<1, 512>>>(lnfw, lnfb, out, out_size);
}

// round 3
// speedup vs baseline: 2.4771x; 2.4771x over previous
#include <cuda_runtime.h>
#include <cuda_bf16.h>
#include <math.h>
#include <stdint.h>

#define T_     8
#define NTOK_  32768
#define D_     128
#define L_     8
#define CD_    64
#define STRB   272          /* bf16 tile row stride in bytes (136 elems) */

// ---------------- device scratch ----------------
__device__ float g_hsum[T_ * L_ * D_];
__device__ int   g_cnt [T_ * L_];
__device__ float g_comp[T_ * L_ * CD_];
__device__ __align__(16) __nv_bfloat16 g_w1img[D_ * 136];  // W1^T padded [e][k]

// ---------------- helpers ----------------
__device__ __forceinline__ uint32_t smem_u32(const void* p) {
    uint32_t a;
    asm("{ .reg .u64 t; cvta.to.shared.u64 t, %1; cvt.u32.u64 %0, t; }" : "=r"(a) : "l"(p));
    return a;
}
#define LDSM4(f, a) asm volatile( \
    "ldmatrix.sync.aligned.m8n8.x4.shared.b16 {%0,%1,%2,%3}, [%4];" \
    : "=r"((f)[0]), "=r"((f)[1]), "=r"((f)[2]), "=r"((f)[3]) : "r"(a))
#define LDSM2T(f, a) asm volatile( \
    "ldmatrix.sync.aligned.m8n8.x2.trans.shared.b16 {%0,%1}, [%2];" \
    : "=r"((f)[0]), "=r"((f)[1]) : "r"(a))
__device__ __forceinline__ void mma16816(float* c, const uint32_t* a, const uint32_t* b) {
    asm volatile(
        "mma.sync.aligned.m16n8k16.row.col.f32.bf16.bf16.f32 "
        "{%0,%1,%2,%3}, {%4,%5,%6,%7}, {%8,%9}, {%0,%1,%2,%3};"
        : "+f"(c[0]), "+f"(c[1]), "+f"(c[2]), "+f"(c[3])
        : "r"(a[0]), "r"(a[1]), "r"(a[2]), "r"(a[3]), "r"(b[0]), "r"(b[1]));
}
__device__ __forceinline__ uint32_t packbf2(float lo, float hi) {
    uint32_t r;
    asm("cvt.rn.bf16x2.f32 %0, %1, %2;" : "=r"(r) : "f"(hi), "f"(lo));
    return r;
}
__device__ __forceinline__ float gelu_exact(float z) {
    return 0.5f * z * (1.0f + erff(z * 0.70710678118654752440f));
}
__device__ __forceinline__ float wred(float v) {
    #pragma unroll
    for (int o = 16; o; o >>= 1) v += __shfl_down_sync(0xffffffffu, v, o);
    return v;
}

// SMEM layout (bytes)
#define OFF_HIST 0
#define OFF_B1S  64                       /* 512B  b1          */
#define OFF_LNW  576                      /* 512B              */
#define OFF_LNB  1088                     /* 512B              */
#define OFF_MASK 1600                     /* 16 x 272 = 4352B  */
#define OFF_XN   6016                     /* 128 x 272 = 34816 (XN, later P) */
#define OFF_W    40832                    /* 128 x 272 = 34816 (W1^T)        */
#define SMEM_SZ  75648

// -------- kernel 0: zero accumulators + bake bf16 W1^T padded image --------
__global__ void k_prep(const float* __restrict__ w1) {
    int i = blockIdx.x * 512 + threadIdx.x;
    if (i < 16384) {
        int e = i & 127, k = i >> 7;
        g_w1img[e * 136 + k] = __float2bfloat16(w1[k * 128 + e]);
    }
    int z = i - 16384;
    if (z >= 0 && z < T_ * L_ * D_) g_hsum[z] = 0.f;
    if (z >= T_ * L_ * D_ && z < T_ * L_ * D_ + T_ * L_) g_cnt[z - T_ * L_ * D_] = 0;
}

// -------- kernel 1: LN -> HMMA GEMM -> gelu -> mask-HMMA bucket sums --------
__global__ __launch_bounds__(512, 2) void k_main(
    const float* __restrict__ x,   const float* __restrict__ lnw,
    const float* __restrict__ lnb, const float* __restrict__ b1,
    const int*   __restrict__ node_idx, const int* __restrict__ ne_p)
{
    extern __shared__ char sm[];
    const uint32_t smb = smem_u32(sm);
    const int tid  = threadIdx.x;
    const int w    = tid >> 5, lane = tid & 31;
    const int t    = blockIdx.y;
    const int base = blockIdx.x * 128;

    int*   hist = (int*)(sm + OFF_HIST);
    float* b1s  = (float*)(sm + OFF_B1S);
    float* lnws = (float*)(sm + OFF_LNW);
    float* lnbs = (float*)(sm + OFF_LNB);

    // ---- phase A: zero mask/hist, stage small vectors, copy W1^T, load x ----
    if (tid < 8) hist[tid] = 0;
    if (tid < 272) ((int4*)(sm + OFF_MASK))[tid] = make_int4(0, 0, 0, 0);
    if (tid < 128) {
        lnws[tid] = lnw[tid];
        b1s[tid]  = b1[tid];
    } else if (tid < 256) {
        lnbs[tid - 128] = lnb[tid - 128];
    }
    {
        const int4* src = (const int4*)g_w1img;
        int4* dst = (int4*)(sm + OFF_W);
        #pragma unroll
        for (int i = tid; i < 2176; i += 512) dst[i] = src[i];
    }
    const int r0 = tid >> 2, q = tid & 3;
    float4 xv[8];
    {
        const float4* xp = (const float4*)(x + ((size_t)t * NTOK_ + base + r0) * D_ + q * 32);
        #pragma unroll
        for (int i = 0; i < 8; ++i) xv[i] = xp[i];
    }
    __syncthreads();

    // ---- phase B: mask ones + hist, LayerNorm -> bf16 XN tile ----
    if (tid < 128) {
        int gsz = ne_p[0] >> 3;
        int gid = node_idx[t * NTOK_ + base + tid] / gsz;
        atomicAdd(&hist[gid], 1);
        *(__nv_bfloat16*)(sm + OFF_MASK + gid * STRB + tid * 2) = __float2bfloat16(1.0f);
    }
    {
        float s = 0.f, s2 = 0.f;
        #pragma unroll
        for (int i = 0; i < 8; ++i) {
            s  += xv[i].x + xv[i].y + xv[i].z + xv[i].w;
            s2 += xv[i].x * xv[i].x + xv[i].y * xv[i].y + xv[i].z * xv[i].z + xv[i].w * xv[i].w;
        }
        s  += __shfl_xor_sync(0xffffffffu, s, 1);  s  += __shfl_xor_sync(0xffffffffu, s, 2);
        s2 += __shfl_xor_sync(0xffffffffu, s2, 1); s2 += __shfl_xor_sync(0xffffffffu, s2, 2);
        float m    = s * (1.0f / 128.0f);
        float rstd = rsqrtf(s2 * (1.0f / 128.0f) - m * m + 1e-5f);
        char* row = sm + OFF_XN + r0 * STRB;
        #pragma unroll
        for (int i = 0; i < 8; ++i) {
            int k0 = q * 32 + i * 4;
            float v0 = (xv[i].x - m) * rstd * lnws[k0 + 0] + lnbs[k0 + 0];
            float v1 = (xv[i].y - m) * rstd * lnws[k0 + 1] + lnbs[k0 + 1];
            float v2 = (xv[i].z - m) * rstd * lnws[k0 + 2] + lnbs[k0 + 2];
            float v3 = (xv[i].w - m) * rstd * lnws[k0 + 3] + lnbs[k0 + 3];
            *(uint2*)(row + k0 * 2) = make_uint2(packbf2(v0, v1), packbf2(v2, v3));
        }
    }
    __syncthreads();

    // ---- MMA1: H[128 tok][128 hid] = XN @ W1 ----
    const int mrow = (w & 7) * 16;          // 16-row m-tile
    const int ncol = (w >> 3) * 64;         // 64-col n-half
    const int lr = lane & 7, lg = lane >> 3;

    float acc[8][4];
    #pragma unroll
    for (int j = 0; j < 8; ++j)
        #pragma unroll
        for (int v = 0; v < 4; ++v) acc[j][v] = 0.f;

    uint32_t aA = smb + OFF_XN + (mrow + lr + (lg & 1) * 8) * STRB + (lg >> 1) * 16;
    uint32_t aB[4];
    #pragma unroll
    for (int p = 0; p < 4; ++p)
        aB[p] = smb + OFF_W + (ncol + p * 16 + lr + (lane >> 4) * 8) * STRB
              + ((lane >> 3) & 1) * 16;

    #pragma unroll
    for (int ks = 0; ks < 8; ++ks) {
        uint32_t af[4];
        LDSM4(af, aA); aA += 32;
        #pragma unroll
        for (int p = 0; p < 4; ++p) {
            uint32_t bf[4];
            LDSM4(bf, aB[p]); aB[p] += 32;
            mma16816(acc[2 * p],     af, bf);
            mma16816(acc[2 * p + 1], af, bf + 2);
        }
    }
    __syncthreads();   // all warps done reading XN before overwrite with P

    // ---- epilogue: P = gelu(H + b1) stored bf16 into XN region ----
    {
        const int m0 = mrow + (lane >> 2);
        char* prow0 = sm + OFF_XN + m0 * STRB;
        char* prow1 = prow0 + 8 * STRB;
        #pragma unroll
        for (int j = 0; j < 8; ++j) {
            int col = ncol + j * 8 + 2 * (lane & 3);
            float bv0 = b1s[col], bv1 = b1s[col + 1];
            float v0 = gelu_exact(acc[j][0] + bv0);
            float v1 = gelu_exact(acc[j][1] + bv1);
            float v2 = gelu_exact(acc[j][2] + bv0);
            float v3 = gelu_exact(acc[j][3] + bv1);
            *(uint32_t*)(prow0 + col * 2) = packbf2(v0, v1);
            *(uint32_t*)(prow1 + col * 2) = packbf2(v2, v3);
        }
    }
    __syncthreads();

    // ---- MMA2: S[16 grp][128 hid] = mask @ P ; warp w owns 8 hidden cols ----
    {
        float a2[4] = {0.f, 0.f, 0.f, 0.f};
        uint32_t aM = smb + OFF_MASK + (lr + (lg & 1) * 8) * STRB + (lg >> 1) * 16;
        uint32_t aP = smb + OFF_XN + ((lane & 7) + ((lane >> 3) & 1) * 8) * STRB + w * 16;
        #pragma unroll
        for (int ks = 0; ks < 8; ++ks) {
            uint32_t mf[4], pf[2];
            LDSM4(mf, aM); aM += 32;
            LDSM2T(pf, aP); aP += 16 * STRB;
            mma16816(a2, mf, pf);
        }
        int grp = lane >> 2;                 // rows 0..7 = groups (8..15 are zero)
        int col = w * 8 + 2 * (lane & 3);
        float* dst = &g_hsum[(t * L_ + grp) * D_ + col];
        atomicAdd(dst,     a2[0]);
        atomicAdd(dst + 1, a2[1]);
    }
    if (tid < 8) atomicAdd(&g_cnt[t * L_ + tid], hist[tid]);
}

// -------- kernel 2: comp = mean-h @ w2 + b2 ; final LN ; exact ortho loss --------
__global__ __launch_bounds__(512) void k_fin(
    const float* __restrict__ w2,   const float* __restrict__ b1,
    const float* __restrict__ b2,   const int*   __restrict__ ne_p,
    const float* __restrict__ lnfw, const float* __restrict__ lnfb,
    float* __restrict__ out, int out_size)
{
    extern __shared__ float dyn[];
    float* mh  = dyn;            // 64 x 128
    float* w2s = mh + 64 * 128;  // 128 x 64
    float* cs  = w2s + 128 * 64; // 64 x 64 (t-major: cs[t*512 + l*64 + c])
    __shared__ float inv[L_];
    __shared__ float dots[49];

    const int tid = threadIdx.x;
    const int g   = ne_p[0] / L_;
    for (int i = tid; i < 128 * 64; i += 512) w2s[i] = w2[i];
    for (int i = tid; i < 64 * 128; i += 512) {
        int p = i >> 7, e = i & 127;
        float h0 = gelu_exact(b1[e]);
        mh[i] = (g_hsum[i] + (float)(g - g_cnt[p]) * h0) / (float)g;
    }
    __syncthreads();

    for (int o = tid; o < 4096; o += 512) {
        int p = o >> 6, c = o & 63;
        float a = b2[c];
        const float* mhp = mh + p * 128;
        #pragma unroll 4
        for (int e = 0; e < 128; ++e) a = fmaf(mhp[e], w2s[e * 64 + c], a);
        cs[o] = a;
        g_comp[o] = a;
    }
    __syncthreads();

    const int w = tid >> 5, lane = tid & 31;
    if (w < 8) {
        const int t = w;
        const float* row = cs + t * 512;
        float s = 0.f;
        for (int i = lane; i < 512; i += 32) s += row[i];
        s = wred(s);
        float m = __shfl_sync(0xffffffffu, s, 0) * (1.0f / 512.0f);
        float v = 0.f;
        for (int i = lane; i < 512; i += 32) { float c0 = row[i] - m; v += c0 * c0; }
        v = wred(v);
        float rstd = rsqrtf(__shfl_sync(0xffffffffu, v, 0) * (1.0f / 512.0f) + 1e-5f);
        for (int i = lane; i < 512; i += 32)
            out[t * 512 + i] = (row[i] - m) * rstd * lnfw[i] + lnfb[i];
    } else {
        const int l = w - 8;
        float s = 0.f;
        for (int k = lane; k < 512; k += 32) {
            float v = cs[(k >> 6) * 512 + l * 64 + (k & 63)];
            s += v * v;
        }
        s = wred(s);
        if (lane == 0) inv[l] = rsqrtf(s);
    }
    __syncthreads();

    for (int p = w; p < 49; p += 16) {
        int i = p / 7, j = p % 7 + 1;
        float ii = inv[i], ij = inv[j];
        float num = 0.f, den = 0.f;
        for (int k = lane; k < 512; k += 32) {
            int off = (k >> 6) * 512 + (k & 63);
            float vi = cs[off + i * 64] * ii;
            float vj = cs[off + j * 64] * ij;
            num += vi * vj;
            den += vi + vj;
        }
        num = wred(num);
        den = wred(den);
        if (lane == 0) { float d = num / den; dots[p] = d * d; }
    }
    __syncthreads();
    if (tid == 0 && out_size > T_ * L_ * CD_) {
        float s = 0.f;
        #pragma unroll
        for (int p = 0; p < 49; ++p) s += dots[p];
        out[T_ * L_ * CD_] = s * (1.0f / 49.0f);
    }
}

// -------- launch --------
extern "C" void kernel_launch(void* const* d_in, const int* in_sizes, int n_in,
                              void* d_out, int out_size)
{
    const float* x    = (const float*)d_in[0];
    const float* lnw  = (const float*)d_in[1];
    const float* lnb  = (const float*)d_in[2];
    const float* w1   = (const float*)d_in[3];
    const float* b1   = (const float*)d_in[4];
    const float* w2   = (const float*)d_in[5];
    const float* b2   = (const float*)d_in[6];
    const float* lnfw = (const float*)d_in[7];
    const float* lnfb = (const float*)d_in[8];
    // d_in[9] = padded_node_mask (all-true)
    const int* node_idx = (const int*)d_in[10];
    const int* ne       = (const int*)d_in[11];
    float* out = (float*)d_out;

    cudaFuncSetAttribute(k_main, cudaFuncAttributeMaxDynamicSharedMemorySize, SMEM_SZ);
    size_t fin_smem = (64 * 128 + 128 * 64 + 64 * 64) * sizeof(float);
    cudaFuncSetAttribute(k_fin, cudaFuncAttributeMaxDynamicSharedMemorySize, (int)fin_smem);

    k_prep<<<49, 512>>>(w1);
    dim3 grid(NTOK_ / 128, T_);
    k_main<<<grid, 512, SMEM_SZ>>>(x, lnw, lnb, b1, node_idx, ne);
    k_fin<<<1, 512, fin_smem>>>(w2, b1, b2, ne, lnfw, lnfb, out, out_size);
}

// round 4
// speedup vs baseline: 2.9097x; 1.1747x over previous
#include <cuda_runtime.h>
#include <cuda_fp16.h>
#include <math.h>
#include <stdint.h>

#define T_     8
#define NTOK_  32768
#define D_     128
#define L_     8
#define CD_    64
#define STRB   272          /* fp16 tile row stride in bytes (136 elems) */

// ---------------- device scratch ----------------
__device__ float g_hsum[T_ * L_ * D_];
__device__ int   g_cnt [T_ * L_];
__device__ float g_c1  [D_];            // sum_k lnw_k * w1[k,e]
__device__ float g_c2b [D_];            // sum_k lnb_k * w1[k,e] + b1[e]
__device__ __align__(16) __half g_w1img[D_ * 136];  // (lnw .* W1)^T padded [e][k]

// ---------------- helpers ----------------
__device__ __forceinline__ uint32_t smem_u32(const void* p) {
    uint32_t a;
    asm("{ .reg .u64 t; cvta.to.shared.u64 t, %1; cvt.u32.u64 %0, t; }" : "=r"(a) : "l"(p));
    return a;
}
#define LDSM4(f, a) asm volatile( \
    "ldmatrix.sync.aligned.m8n8.x4.shared.b16 {%0,%1,%2,%3}, [%4];" \
    : "=r"((f)[0]), "=r"((f)[1]), "=r"((f)[2]), "=r"((f)[3]) : "r"(a))
#define LDSM2T(f, a) asm volatile( \
    "ldmatrix.sync.aligned.m8n8.x2.trans.shared.b16 {%0,%1}, [%2];" \
    : "=r"((f)[0]), "=r"((f)[1]) : "r"(a))
__device__ __forceinline__ void mma16816(float* c, const uint32_t* a, const uint32_t* b) {
    asm volatile(
        "mma.sync.aligned.m16n8k16.row.col.f32.f16.f16.f32 "
        "{%0,%1,%2,%3}, {%4,%5,%6,%7}, {%8,%9}, {%0,%1,%2,%3};"
        : "+f"(c[0]), "+f"(c[1]), "+f"(c[2]), "+f"(c[3])
        : "r"(a[0]), "r"(a[1]), "r"(a[2]), "r"(a[3]), "r"(b[0]), "r"(b[1]));
}
__device__ __forceinline__ uint32_t packhf2(float lo, float hi) {
    uint32_t r;
    asm("cvt.rn.f16x2.f32 %0, %1, %2;" : "=r"(r) : "f"(hi), "f"(lo));
    return r;
}
__device__ __forceinline__ float gelu_exact(float z) {
    return 0.5f * z * (1.0f + erff(z * 0.70710678118654752440f));
}
__device__ __forceinline__ float wred(float v) {
    #pragma unroll
    for (int o = 16; o; o >>= 1) v += __shfl_down_sync(0xffffffffu, v, o);
    return v;
}

// SMEM layout (bytes)
#define OFF_HIST 0
#define OFF_STAT 64          /* 128 x float2 (m, rstd)          */
#define OFF_C1   1088        /* 512B                            */
#define OFF_C2B  1600        /* 512B                            */
#define OFF_MASK 2112        /* 16 x 272 = 4352B                */
#define OFF_XN   6528        /* 128 x 272 (X fp16, later P)     */
#define OFF_W    41344       /* 128 x 272 (W1' ^T fp16)         */
#define SMEM_SZ  76160

// -------- kernel 0: accumulator zero + W1' image + c1/c2b vectors --------
__global__ void k_prep(const float* __restrict__ w1, const float* __restrict__ lnw,
                       const float* __restrict__ lnb, const float* __restrict__ b1) {
    __shared__ float pa[512], pb[512];
    const int b = blockIdx.x, tid = threadIdx.x;
    if (b < 49) {
        int i = b * 512 + tid;
        if (i < 16384) {
            int e = i & 127, k = i >> 7;
            g_w1img[e * 136 + k] = __float2half(lnw[k] * w1[k * 128 + e]);
        }
        int z = i - 16384;
        if (z >= 0 && z < T_ * L_ * D_) g_hsum[z] = 0.f;
        if (z >= T_ * L_ * D_ && z < T_ * L_ * D_ + T_ * L_) g_cnt[z - T_ * L_ * D_] = 0;
    } else {
        const int e = tid & 127, j = tid >> 7;
        float a = 0.f, c = 0.f;
        #pragma unroll 4
        for (int kk = 0; kk < 32; ++kk) {
            int k = j * 32 + kk;
            float wv = w1[k * 128 + e];
            a = fmaf(lnw[k], wv, a);
            c = fmaf(lnb[k], wv, c);
        }
        pa[tid] = a; pb[tid] = c;
        __syncthreads();
        if (tid < 128) {
            g_c1[tid]  = pa[tid] + pa[tid + 128] + pa[tid + 256] + pa[tid + 384];
            g_c2b[tid] = pb[tid] + pb[tid + 128] + pb[tid + 256] + pb[tid + 384] + b1[tid];
        }
    }
}

// -------- kernel 1: x -> HMMA GEMM -> LN-affine + gelu -> mask-HMMA sums --------
__global__ __launch_bounds__(512, 2) void k_main(
    const float* __restrict__ x, const int* __restrict__ node_idx,
    const int* __restrict__ ne_p)
{
    extern __shared__ char sm[];
    const uint32_t smb = smem_u32(sm);
    const int tid  = threadIdx.x;
    const int w    = tid >> 5, lane = tid & 31;
    const int t    = blockIdx.y;
    const int base = blockIdx.x * 128;

    int*    hist = (int*)(sm + OFF_HIST);
    float2* stat = (float2*)(sm + OFF_STAT);
    float*  c1s  = (float*)(sm + OFF_C1);
    float*  c2bs = (float*)(sm + OFF_C2B);

    // ---- phase A: zero mask/hist, stage consts, copy W', load x ----
    if (tid < 8) hist[tid] = 0;
    if (tid < 272) ((int4*)(sm + OFF_MASK))[tid] = make_int4(0, 0, 0, 0);
    if (tid < 128)      c1s[tid] = g_c1[tid];
    else if (tid < 256) c2bs[tid - 128] = g_c2b[tid - 128];
    {
        const int4* src = (const int4*)g_w1img;
        int4* dst = (int4*)(sm + OFF_W);
        #pragma unroll
        for (int i = tid; i < 2176; i += 512) dst[i] = src[i];
    }
    const int r0 = tid >> 2, q = tid & 3;
    float4 xv[8];
    {
        const float4* xp = (const float4*)(x + ((size_t)t * NTOK_ + base + r0) * D_ + q * 32);
        #pragma unroll
        for (int i = 0; i < 8; ++i) xv[i] = xp[i];
    }
    // store raw x as fp16 immediately (no LN dependency)
    {
        char* row = sm + OFF_XN + r0 * STRB + q * 64;
        #pragma unroll
        for (int i = 0; i < 8; ++i)
            *(uint2*)(row + i * 8) =
                make_uint2(packhf2(xv[i].x, xv[i].y), packhf2(xv[i].z, xv[i].w));
    }
    // stats in parallel
    {
        float s = 0.f, s2 = 0.f;
        #pragma unroll
        for (int i = 0; i < 8; ++i) {
            s  += xv[i].x + xv[i].y + xv[i].z + xv[i].w;
            s2 += xv[i].x * xv[i].x + xv[i].y * xv[i].y + xv[i].z * xv[i].z + xv[i].w * xv[i].w;
        }
        s  += __shfl_xor_sync(0xffffffffu, s, 1);  s  += __shfl_xor_sync(0xffffffffu, s, 2);
        s2 += __shfl_xor_sync(0xffffffffu, s2, 1); s2 += __shfl_xor_sync(0xffffffffu, s2, 2);
        float m    = s * (1.0f / 128.0f);
        float rstd = rsqrtf(s2 * (1.0f / 128.0f) - m * m + 1e-5f);
        if (q == 0) stat[r0] = make_float2(m, rstd);
    }
    __syncthreads();   // mask zero visible

    if (tid < 128) {
        int gsz = ne_p[0] >> 3;
        int gid = node_idx[t * NTOK_ + base + tid] / gsz;
        atomicAdd(&hist[gid], 1);
        *(__half*)(sm + OFF_MASK + gid * STRB + tid * 2) = __float2half(1.0f);
    }
    __syncthreads();   // XN, W, mask, stats all ready

    // ---- MMA1: G[128 tok][128 hid] = X @ W1' ----
    const int mrow = (w & 7) * 16;
    const int ncol = (w >> 3) * 64;
    const int lr = lane & 7, lg = lane >> 3;

    float acc[8][4];
    #pragma unroll
    for (int j = 0; j < 8; ++j)
        #pragma unroll
        for (int v = 0; v < 4; ++v) acc[j][v] = 0.f;

    uint32_t aA = smb + OFF_XN + (mrow + lr + (lg & 1) * 8) * STRB + (lg >> 1) * 16;
    uint32_t aB[4];
    #pragma unroll
    for (int p = 0; p < 4; ++p)
        aB[p] = smb + OFF_W + (ncol + p * 16 + lr + (lane >> 4) * 8) * STRB
              + ((lane >> 3) & 1) * 16;

    #pragma unroll
    for (int ks = 0; ks < 8; ++ks) {
        uint32_t af[4];
        LDSM4(af, aA); aA += 32;
        #pragma unroll
        for (int p = 0; p < 4; ++p) {
            uint32_t bf[4];
            LDSM4(bf, aB[p]); aB[p] += 32;
            mma16816(acc[2 * p],     af, bf);
            mma16816(acc[2 * p + 1], af, bf + 2);
        }
    }
    __syncthreads();   // all warps done reading X tile before overwrite with P

    // ---- epilogue: h = r*g - (r*m)*c1 + c2b ; P = gelu(h) fp16 ----
    {
        const int row0 = mrow + (lane >> 2);
        float2 st0 = stat[row0], st1 = stat[row0 + 8];
        float r0f = st0.y, rm0 = st0.y * st0.x;
        float r1f = st1.y, rm1 = st1.y * st1.x;
        char* prow0 = sm + OFF_XN + row0 * STRB;
        char* prow1 = prow0 + 8 * STRB;
        #pragma unroll
        for (int j = 0; j < 8; ++j) {
            int col = ncol + j * 8 + 2 * (lane & 3);
            float2 c1p = *(float2*)(c1s + col);
            float2 c2p = *(float2*)(c2bs + col);
            float h0 = fmaf(r0f, acc[j][0], fmaf(-rm0, c1p.x, c2p.x));
            float h1 = fmaf(r0f, acc[j][1], fmaf(-rm0, c1p.y, c2p.y));
            float h2 = fmaf(r1f, acc[j][2], fmaf(-rm1, c1p.x, c2p.x));
            float h3 = fmaf(r1f, acc[j][3], fmaf(-rm1, c1p.y, c2p.y));
            *(uint32_t*)(prow0 + col * 2) = packhf2(gelu_exact(h0), gelu_exact(h1));
            *(uint32_t*)(prow1 + col * 2) = packhf2(gelu_exact(h2), gelu_exact(h3));
        }
    }
    __syncthreads();

    // ---- MMA2: S[16 grp][128 hid] = mask @ P ; warp w owns 8 hidden cols ----
    {
        float a2[4] = {0.f, 0.f, 0.f, 0.f};
        uint32_t aM = smb + OFF_MASK + (lr + (lg & 1) * 8) * STRB + (lg >> 1) * 16;
        uint32_t aP = smb + OFF_XN + ((lane & 7) + ((lane >> 3) & 1) * 8) * STRB + w * 16;
        #pragma unroll
        for (int ks = 0; ks < 8; ++ks) {
            uint32_t mf[4], pf[2];
            LDSM4(mf, aM); aM += 32;
            LDSM2T(pf, aP); aP += 16 * STRB;
            mma16816(a2, mf, pf);
        }
        int grp = lane >> 2;
        int col = w * 8 + 2 * (lane & 3);
        float* dst = &g_hsum[(t * L_ + grp) * D_ + col];
        atomicAdd(dst,     a2[0]);
        atomicAdd(dst + 1, a2[1]);
    }
    if (tid < 8) atomicAdd(&g_cnt[t * L_ + tid], hist[tid]);
}

// -------- kernel 2: comp = mean-h @ w2 + b2 ; final LN ; exact ortho loss --------
__global__ __launch_bounds__(1024) void k_fin(
    const float* __restrict__ w2,   const float* __restrict__ b1,
    const float* __restrict__ b2,   const int*   __restrict__ ne_p,
    const float* __restrict__ lnfw, const float* __restrict__ lnfb,
    float* __restrict__ out, int out_size)
{
    extern __shared__ float dyn[];
    float* w2t = dyn;              // 64 x 132 (padded, transposed)
    float* mh  = w2t + 64 * 132;   // 64 x 128
    float* cs  = mh + 64 * 128;    // 64 x 64 (t-major)
    __shared__ float inv[L_];
    __shared__ float dots[49];

    const int tid = threadIdx.x;
    const int g   = ne_p[0] / L_;
    for (int i = tid; i < 8192; i += 1024) {
        int c = i & 63, e = i >> 6;
        w2t[c * 132 + e] = w2[e * 64 + c];
    }
    for (int i = tid; i < 8192; i += 1024) {
        int p = i >> 7, e = i & 127;
        float h0 = gelu_exact(b1[e]);
        mh[i] = (g_hsum[i] + (float)(g - g_cnt[p]) * h0) / (float)g;
    }
    __syncthreads();

    // comp: thread -> (c, 4 consecutive p)
    {
        const int c = tid & 63, qq = tid >> 6;   // qq 0..15
        float a0 = b2[c], a1 = a0, a2 = a0, a3 = a0;
        const float* m0 = mh + (qq * 4 + 0) * 128;
        const float* m1 = mh + (qq * 4 + 1) * 128;
        const float* m2 = mh + (qq * 4 + 2) * 128;
        const float* m3 = mh + (qq * 4 + 3) * 128;
        #pragma unroll 8
        for (int e = 0; e < 128; e += 4) {
            float4 wv = *(const float4*)(w2t + c * 132 + e);
            float4 v0 = *(const float4*)(m0 + e);
            float4 v1 = *(const float4*)(m1 + e);
            float4 v2 = *(const float4*)(m2 + e);
            float4 v3 = *(const float4*)(m3 + e);
            a0 += wv.x * v0.x + wv.y * v0.y + wv.z * v0.z + wv.w * v0.w;
            a1 += wv.x * v1.x + wv.y * v1.y + wv.z * v1.z + wv.w * v1.w;
            a2 += wv.x * v2.x + wv.y * v2.y + wv.z * v2.z + wv.w * v2.w;
            a3 += wv.x * v3.x + wv.y * v3.y + wv.z * v3.z + wv.w * v3.w;
        }
        cs[(qq * 4 + 0) * 64 + c] = a0;
        cs[(qq * 4 + 1) * 64 + c] = a1;
        cs[(qq * 4 + 2) * 64 + c] = a2;
        cs[(qq * 4 + 3) * 64 + c] = a3;
    }
    __syncthreads();

    const int w = tid >> 5, lane = tid & 31;
    if (w < 8) {
        const int t = w;
        const float* row = cs + t * 512;
        float s = 0.f;
        for (int i = lane; i < 512; i += 32) s += row[i];
        s = wred(s);
        float m = __shfl_sync(0xffffffffu, s, 0) * (1.0f / 512.0f);
        float v = 0.f;
        for (int i = lane; i < 512; i += 32) { float c0 = row[i] - m; v += c0 * c0; }
        v = wred(v);
        float rstd = rsqrtf(__shfl_sync(0xffffffffu, v, 0) * (1.0f / 512.0f) + 1e-5f);
        for (int i = lane; i < 512; i += 32)
            out[t * 512 + i] = (row[i] - m) * rstd * lnfw[i] + lnfb[i];
    } else if (w < 16) {
        const int l = w - 8;
        float s = 0.f;
        for (int k = lane; k < 512; k += 32) {
            float v = cs[(k >> 6) * 512 + l * 64 + (k & 63)];
            s += v * v;
        }
        s = wred(s);
        if (lane == 0) inv[l] = rsqrtf(s);
    }
    __syncthreads();

    for (int p = w; p < 49; p += 32) {
        int i = p / 7, j = p % 7 + 1;
        float ii = inv[i], ij = inv[j];
        float num = 0.f, den = 0.f;
        for (int k = lane; k < 512; k += 32) {
            int off = (k >> 6) * 512 + (k & 63);
            float vi = cs[off + i * 64] * ii;
            float vj = cs[off + j * 64] * ij;
            num += vi * vj;
            den += vi + vj;
        }
        num = wred(num);
        den = wred(den);
        if (lane == 0) { float d = num / den; dots[p] = d * d; }
    }
    __syncthreads();
    if (tid == 0 && out_size > T_ * L_ * CD_) {
        float s = 0.f;
        #pragma unroll
        for (int p = 0; p < 49; ++p) s += dots[p];
        out[T_ * L_ * CD_] = s * (1.0f / 49.0f);
    }
}

// -------- launch --------
extern "C" void kernel_launch(void* const* d_in, const int* in_sizes, int n_in,
                              void* d_out, int out_size)
{
    const float* x    = (const float*)d_in[0];
    const float* lnw  = (const float*)d_in[1];
    const float* lnb  = (const float*)d_in[2];
    const float* w1   = (const float*)d_in[3];
    const float* b1   = (const float*)d_in[4];
    const float* w2   = (const float*)d_in[5];
    const float* b2   = (const float*)d_in[6];
    const float* lnfw = (const float*)d_in[7];
    const float* lnfb = (const float*)d_in[8];
    // d_in[9] = padded_node_mask (all-true)
    const int* node_idx = (const int*)d_in[10];
    const int* ne       = (const int*)d_in[11];
    float* out = (float*)d_out;

    cudaFuncSetAttribute(k_main, cudaFuncAttributeMaxDynamicSharedMemorySize, SMEM_SZ);
    size_t fin_smem = (64 * 132 + 64 * 128 + 64 * 64) * sizeof(float);
    cudaFuncSetAttribute(k_fin, cudaFuncAttributeMaxDynamicSharedMemorySize, (int)fin_smem);

    k_prep<<<50, 512>>>(w1, lnw, lnb, b1);
    dim3 grid(NTOK_ / 128, T_);
    k_main<<<grid, 512, SMEM_SZ>>>(x, node_idx, ne);
    k_fin<<<1, 1024, fin_smem>>>(w2, b1, b2, ne, lnfw, lnfb, out, out_size);
}